// round 12
// baseline (speedup 1.0000x reference)
#include <cuda_runtime.h>
#include <cuda_bf16.h>
#include <cstdint>

// ---------------- problem constants ----------------
#define NNODES 50000
#define INCH   256
#define HEADS  4
#define CPH    64
#define HC     256
#define HOPS   3
#define EDGES  400000
#define NEG_SLOPE 0.2f
#define NSCANB 49               // ceil(50000/1024)

// ---------------- scratch (static device memory) ----------------
__device__ float g_XL[NNODES * HC];
__device__ float g_XR[NNODES * HC];
__device__ float g_GW[NNODES * HOPS];
__device__ int   g_CNT[HOPS * NNODES];
__device__ int   g_ROW[HOPS * NNODES];
__device__ int   g_POS[HOPS * NNODES];
__device__ int   g_BSUM[HOPS][64];
__device__ int   g_CSR[HOPS * EDGES];
__device__ int2  g_META[HOPS * NNODES];   // (row_start, count) fused

// ---------------- helpers ----------------
__device__ __forceinline__ float lrelu(float v) { return v > 0.f ? v : NEG_SLOPE * v; }

__device__ __forceinline__ void red_add_v4(float* p, float4 v) {
    asm volatile("red.global.add.v4.f32 [%0], {%1,%2,%3,%4};"
                 :: "l"(p), "f"(v.x), "f"(v.y), "f"(v.z), "f"(v.w) : "memory");
}
__device__ __forceinline__ unsigned long long pack_dup(float v) {
    unsigned long long d;
    asm("mov.b64 %0, {%1, %1};" : "=l"(d) : "r"(__float_as_uint(v)));
    return d;
}
__device__ __forceinline__ void ffma2(unsigned long long& acc,
                                      unsigned long long a, unsigned long long b) {
    asm("fma.rn.f32x2 %0, %1, %2, %0;" : "+l"(acc) : "l"(a), "l"(b));
}
__device__ __forceinline__ void unpack2(unsigned long long p, float& lo, float& hi) {
    unsigned l, h;
    asm("mov.b64 {%0, %1}, %2;" : "=r"(l), "=r"(h) : "l"(p));
    lo = __uint_as_float(l); hi = __uint_as_float(h);
}

// per-edge logit: lrelu(xl+xr).att, reduced over the 8 lanes of each head
__device__ __forceinline__ float edge_logit(float4 a0, float4 a1,
                                            float4 r0, float4 r1,
                                            float4 t0, float4 t1) {
    float p = lrelu(a0.x + r0.x) * t0.x + lrelu(a0.y + r0.y) * t0.y
            + lrelu(a0.z + r0.z) * t0.z + lrelu(a0.w + r0.w) * t0.w
            + lrelu(a1.x + r1.x) * t1.x + lrelu(a1.y + r1.y) * t1.y
            + lrelu(a1.z + r1.z) * t1.z + lrelu(a1.w + r1.w) * t1.w;
    p += __shfl_xor_sync(0xffffffffu, p, 1);
    p += __shfl_xor_sync(0xffffffffu, p, 2);
    p += __shfl_xor_sync(0xffffffffu, p, 4);
    return p;
}

// ---------------- zero: counters (side stream) ----------------
__global__ __launch_bounds__(256)
void zero_cnt() {
    int i = blockIdx.x * blockDim.x + threadIdx.x;
    if (i < HOPS * NNODES / 4)
        ((int4*)g_CNT)[i] = make_int4(0, 0, 0, 0);
}
// ---------------- zero: output (side stream) ----------------
__global__ __launch_bounds__(256)
void zero_out(float* __restrict__ out) {
    int i = blockIdx.x * blockDim.x + threadIdx.x;
    if (i < NNODES * CPH / 4)
        ((float4*)out)[i] = make_float4(0.f, 0.f, 0.f, 0.f);
}

// ---------------- SGEMM (packed f32x2), both weights via blockIdx.z ----------------
__global__ __launch_bounds__(256)
void sgemm2_dual(const float* __restrict__ A,
                 const float* __restrict__ WL, const float* __restrict__ bL,
                 const float* __restrict__ WR, const float* __restrict__ bR,
                 float* __restrict__ XL, float* __restrict__ XR) {
    __shared__ unsigned long long Asd[2][8][128];
    __shared__ float Bs[2][8][128];

    const float* B    = blockIdx.z ? WR : WL;
    const float* bias = blockIdx.z ? bR : bL;
    float*       Cm   = blockIdx.z ? XR : XL;

    const int tid = threadIdx.x;
    const int tx = tid & 15, ty = tid >> 4;
    const int row0 = blockIdx.y * 128;
    const int col0 = blockIdx.x * 128;
    const int aRow = tid >> 1, aCol = (tid & 1) * 4;
    const int bRow = tid >> 5, bCol = (tid & 31) * 4;

    unsigned long long acc[8][4];
    #pragma unroll
    for (int i = 0; i < 8; i++)
        #pragma unroll
        for (int j = 0; j < 4; j++) acc[i][j] = 0ull;

    {
        float4 av = make_float4(0.f, 0.f, 0.f, 0.f);
        if (row0 + aRow < NNODES)
            av = *(const float4*)(A + (size_t)(row0 + aRow) * 256 + aCol);
        Asd[0][aCol + 0][aRow] = pack_dup(av.x);
        Asd[0][aCol + 1][aRow] = pack_dup(av.y);
        Asd[0][aCol + 2][aRow] = pack_dup(av.z);
        Asd[0][aCol + 3][aRow] = pack_dup(av.w);
        *(float4*)&Bs[0][bRow][bCol] =
            *(const float4*)(B + (size_t)bRow * 256 + col0 + bCol);
    }
    __syncthreads();

    #pragma unroll 1
    for (int kt = 0; kt < 32; kt++) {
        const int cur = kt & 1, nxt = cur ^ 1;
        float4 av, bv;
        const bool pf = (kt < 31);
        if (pf) {
            av = make_float4(0.f, 0.f, 0.f, 0.f);
            if (row0 + aRow < NNODES)
                av = *(const float4*)(A + (size_t)(row0 + aRow) * 256 + (kt + 1) * 8 + aCol);
            bv = *(const float4*)(B + (size_t)((kt + 1) * 8 + bRow) * 256 + col0 + bCol);
        }

        #pragma unroll
        for (int k = 0; k < 8; k++) {
            unsigned long long ad[8], bp[4];
            *(ulonglong2*)&ad[0] = *(ulonglong2*)&Asd[cur][k][ty * 8 + 0];
            *(ulonglong2*)&ad[2] = *(ulonglong2*)&Asd[cur][k][ty * 8 + 2];
            *(ulonglong2*)&ad[4] = *(ulonglong2*)&Asd[cur][k][ty * 8 + 4];
            *(ulonglong2*)&ad[6] = *(ulonglong2*)&Asd[cur][k][ty * 8 + 6];
            *(ulonglong2*)&bp[0] = *(ulonglong2*)&Bs[cur][k][tx * 8 + 0];
            *(ulonglong2*)&bp[2] = *(ulonglong2*)&Bs[cur][k][tx * 8 + 4];
            #pragma unroll
            for (int i = 0; i < 8; i++)
                #pragma unroll
                for (int j = 0; j < 4; j++)
                    ffma2(acc[i][j], ad[i], bp[j]);
        }

        if (pf) {
            Asd[nxt][aCol + 0][aRow] = pack_dup(av.x);
            Asd[nxt][aCol + 1][aRow] = pack_dup(av.y);
            Asd[nxt][aCol + 2][aRow] = pack_dup(av.z);
            Asd[nxt][aCol + 3][aRow] = pack_dup(av.w);
            *(float4*)&Bs[nxt][bRow][bCol] = bv;
        }
        __syncthreads();
    }

    #pragma unroll
    for (int i = 0; i < 8; i++) {
        int r = row0 + ty * 8 + i;
        if (r < NNODES) {
            #pragma unroll
            for (int j = 0; j < 4; j += 2) {
                int cc = col0 + tx * 8 + j * 2;
                float4 o;
                unpack2(acc[i][j + 0], o.x, o.y);
                unpack2(acc[i][j + 1], o.z, o.w);
                o.x += bias[cc + 0]; o.y += bias[cc + 1];
                o.z += bias[cc + 2]; o.w += bias[cc + 3];
                *(float4*)(Cm + (size_t)r * 256 + cc) = o;
            }
        }
    }
}

// ---------------- gate ----------------
__global__ __launch_bounds__(256)
void gate_kernel(const float* __restrict__ x, const float* __restrict__ Wg,
                 const float* __restrict__ bg) {
    int n = blockIdx.x * 8 + (threadIdx.x >> 5);
    if (n >= NNODES) return;
    int lane = threadIdx.x & 31;
    const float* xr = x + (size_t)n * INCH;
    float p0 = 0.f, p1 = 0.f, p2 = 0.f;
    #pragma unroll
    for (int i = 0; i < INCH; i += 32) {
        float xv = xr[i + lane];
        const float* w = Wg + (i + lane) * 3;
        p0 = fmaf(xv, w[0], p0);
        p1 = fmaf(xv, w[1], p1);
        p2 = fmaf(xv, w[2], p2);
    }
    #pragma unroll
    for (int o = 16; o >= 1; o >>= 1) {
        p0 += __shfl_xor_sync(0xffffffffu, p0, o);
        p1 += __shfl_xor_sync(0xffffffffu, p1, o);
        p2 += __shfl_xor_sync(0xffffffffu, p2, o);
    }
    if (lane == 0) {
        p0 += bg[0]; p1 += bg[1]; p2 += bg[2];
        float m = fmaxf(p0, fmaxf(p1, p2));
        float e0 = __expf(p0 - m), e1 = __expf(p1 - m), e2 = __expf(p2 - m);
        float inv = 1.f / (e0 + e1 + e2);
        g_GW[n * 3 + 0] = e0 * inv;
        g_GW[n * 3 + 1] = e1 * inv;
        g_GW[n * 3 + 2] = e2 * inv;
    }
}

// ---------------- CSR build: count / scan / scatter ----------------
__global__ __launch_bounds__(256)
void count_kernel(const int* __restrict__ ei0, const int* __restrict__ ei1,
                  const int* __restrict__ ei2) {
    int hop = blockIdx.y;
    const int* ei = hop == 0 ? ei0 : (hop == 1 ? ei1 : ei2);
    int e = blockIdx.x * 256 + threadIdx.x;
    if (e < EDGES)
        atomicAdd(&g_CNT[hop * NNODES + ei[EDGES + e]], 1);
}

__global__ __launch_bounds__(256)
void scan1_kernel() {
    __shared__ int ws[8];
    int hop = blockIdx.y;
    int base = blockIdx.x * 1024 + threadIdx.x * 4;
    int lane = threadIdx.x & 31, warp = threadIdx.x >> 5;
    int v[4];
    #pragma unroll
    for (int j = 0; j < 4; j++)
        v[j] = (base + j < NNODES) ? g_CNT[hop * NNODES + base + j] : 0;
    int ts = v[0] + v[1] + v[2] + v[3];
    int is = ts;
    #pragma unroll
    for (int o = 1; o < 32; o <<= 1) {
        int t = __shfl_up_sync(0xffffffffu, is, o);
        if (lane >= o) is += t;
    }
    if (lane == 31) ws[warp] = is;
    __syncthreads();
    if (threadIdx.x == 0) {
        int s = 0;
        #pragma unroll
        for (int i = 0; i < 8; i++) { int t = ws[i]; ws[i] = s; s += t; }
        g_BSUM[hop][blockIdx.x] = s;
    }
    __syncthreads();
    int excl = ws[warp] + is - ts;
    #pragma unroll
    for (int j = 0; j < 4; j++) {
        if (base + j < NNODES) g_ROW[hop * NNODES + base + j] = excl;
        excl += v[j];
    }
}

__global__ __launch_bounds__(32)
void scan2_kernel() {
    int hop = blockIdx.x, l = threadIdx.x;
    int a = (l < NSCANB) ? g_BSUM[hop][l] : 0;
    int b = (32 + l < NSCANB) ? g_BSUM[hop][32 + l] : 0;
    int sa = a;
    #pragma unroll
    for (int o = 1; o < 32; o <<= 1) {
        int t = __shfl_up_sync(0xffffffffu, sa, o);
        if (l >= o) sa += t;
    }
    int tot = __shfl_sync(0xffffffffu, sa, 31);
    int sb = b;
    #pragma unroll
    for (int o = 1; o < 32; o <<= 1) {
        int t = __shfl_up_sync(0xffffffffu, sb, o);
        if (l >= o) sb += t;
    }
    sb += tot;
    if (l < NSCANB) g_BSUM[hop][l] = sa - a;
    if (32 + l < NSCANB) g_BSUM[hop][32 + l] = sb - b;
}

__global__ __launch_bounds__(256)
void scan3_kernel() {
    int hop = blockIdx.y;
    int i = blockIdx.x * 256 + threadIdx.x;
    if (i < NNODES) {
        int r = g_ROW[hop * NNODES + i] + g_BSUM[hop][i >> 10];
        g_POS[hop * NNODES + i] = r;
        g_META[hop * NNODES + i] = make_int2(r, g_CNT[hop * NNODES + i]);
    }
}

__global__ __launch_bounds__(256)
void scatter_kernel(const int* __restrict__ ei0, const int* __restrict__ ei1,
                    const int* __restrict__ ei2) {
    int hop = blockIdx.y;
    const int* ei = hop == 0 ? ei0 : (hop == 1 ? ei1 : ei2);
    int e = blockIdx.x * 256 + threadIdx.x;
    if (e < EDGES) {
        int d = ei[EDGES + e];
        int p = atomicAdd(&g_POS[hop * NNODES + d], 1);
        g_CSR[hop * EDGES + p] = ei[e];
    }
}

// ---------------- aggregate: warp per (hop, dst), 2x unrolled, idx-pipelined ----------------
__global__ __launch_bounds__(256)
void aggregate_kernel(const float* __restrict__ att, const float* __restrict__ bias,
                      float* __restrict__ out) {
    int hop = blockIdx.y;
    int d = blockIdx.x * 8 + (threadIdx.x >> 5);
    if (d >= NNODES) return;
    int lane = threadIdx.x & 31;

    int2 meta = __ldg(&g_META[hop * NNODES + d]);   // (row_start, count)
    const int* srcs = g_CSR + (size_t)hop * EDGES + meta.x;
    int cnt = meta.y;

    const float4* xr4 = (const float4*)(g_XR + (size_t)d * HC) + lane * 2;
    float4 r0 = xr4[0], r1 = xr4[1];
    float4 t0 = __ldg((const float4*)(att + hop * HC) + lane * 2);
    float4 t1 = __ldg((const float4*)(att + hop * HC) + lane * 2 + 1);

    float acc[8];
    #pragma unroll
    for (int j = 0; j < 8; j++) acc[j] = 0.f;
    float sumh = 0.f;

    if (hop == 0) {   // self loop: src == d
        const float4* xs = (const float4*)(g_XL + (size_t)d * HC) + lane * 2;
        float4 a0 = xs[0], a1 = xs[1];
        float p = edge_logit(a0, a1, r0, r1, t0, t1);
        float ex = __expf(p);
        sumh = ex;
        acc[0] = ex * a0.x; acc[1] = ex * a0.y; acc[2] = ex * a0.z; acc[3] = ex * a0.w;
        acc[4] = ex * a1.x; acc[5] = ex * a1.y; acc[6] = ex * a1.z; acc[7] = ex * a1.w;
    }

    int e = 0;
    int s0 = 0, s1 = 0;
    if (cnt >= 2) { s0 = __ldg(srcs); s1 = __ldg(srcs + 1); }
    #pragma unroll 1
    for (; e + 2 <= cnt; ) {
        // prefetch next pair of indices before touching this pair's data
        int n0 = 0, n1 = 0;
        const bool more = (e + 4 <= cnt);
        if (more) { n0 = __ldg(srcs + e + 2); n1 = __ldg(srcs + e + 3); }

        const float4* x0 = (const float4*)(g_XL + (size_t)s0 * HC) + lane * 2;
        const float4* x1 = (const float4*)(g_XL + (size_t)s1 * HC) + lane * 2;
        float4 a00 = x0[0], a01 = x0[1];
        float4 a10 = x1[0], a11 = x1[1];

        float p0 = edge_logit(a00, a01, r0, r1, t0, t1);
        float p1 = edge_logit(a10, a11, r0, r1, t0, t1);
        float e0 = __expf(p0), e1 = __expf(p1);
        sumh += e0 + e1;

        acc[0] = fmaf(e0, a00.x, acc[0]); acc[1] = fmaf(e0, a00.y, acc[1]);
        acc[2] = fmaf(e0, a00.z, acc[2]); acc[3] = fmaf(e0, a00.w, acc[3]);
        acc[4] = fmaf(e0, a01.x, acc[4]); acc[5] = fmaf(e0, a01.y, acc[5]);
        acc[6] = fmaf(e0, a01.z, acc[6]); acc[7] = fmaf(e0, a01.w, acc[7]);

        acc[0] = fmaf(e1, a10.x, acc[0]); acc[1] = fmaf(e1, a10.y, acc[1]);
        acc[2] = fmaf(e1, a10.z, acc[2]); acc[3] = fmaf(e1, a10.w, acc[3]);
        acc[4] = fmaf(e1, a11.x, acc[4]); acc[5] = fmaf(e1, a11.y, acc[5]);
        acc[6] = fmaf(e1, a11.z, acc[6]); acc[7] = fmaf(e1, a11.w, acc[7]);

        s0 = n0; s1 = n1; e += 2;
    }
    if (e < cnt) {
        int s = __ldg(srcs + e);
        const float4* xs = (const float4*)(g_XL + (size_t)s * HC) + lane * 2;
        float4 a0 = xs[0], a1 = xs[1];
        float p = edge_logit(a0, a1, r0, r1, t0, t1);
        float ex = __expf(p);
        sumh += ex;
        acc[0] = fmaf(ex, a0.x, acc[0]); acc[1] = fmaf(ex, a0.y, acc[1]);
        acc[2] = fmaf(ex, a0.z, acc[2]); acc[3] = fmaf(ex, a0.w, acc[3]);
        acc[4] = fmaf(ex, a1.x, acc[4]); acc[5] = fmaf(ex, a1.y, acc[5]);
        acc[6] = fmaf(ex, a1.z, acc[6]); acc[7] = fmaf(ex, a1.w, acc[7]);
    }

    float inv = 1.f / (sumh + 1e-16f);
    float r[8];
    #pragma unroll
    for (int j = 0; j < 8; j++) r[j] = acc[j] * inv;
    // mean over heads: combine lanes l, l^8, l^16, l^24
    #pragma unroll
    for (int j = 0; j < 8; j++) {
        r[j] += __shfl_xor_sync(0xffffffffu, r[j], 8);
        r[j] += __shfl_xor_sync(0xffffffffu, r[j], 16);
    }
    if (lane < 8) {
        float gw = g_GW[d * HOPS + hop];
        const float* bb = bias + hop * CPH + lane * 8;
        float4 o0, o1;
        o0.x = (r[0] * 0.25f + __ldg(bb + 0)) * gw;
        o0.y = (r[1] * 0.25f + __ldg(bb + 1)) * gw;
        o0.z = (r[2] * 0.25f + __ldg(bb + 2)) * gw;
        o0.w = (r[3] * 0.25f + __ldg(bb + 3)) * gw;
        o1.x = (r[4] * 0.25f + __ldg(bb + 4)) * gw;
        o1.y = (r[5] * 0.25f + __ldg(bb + 5)) * gw;
        o1.z = (r[6] * 0.25f + __ldg(bb + 6)) * gw;
        o1.w = (r[7] * 0.25f + __ldg(bb + 7)) * gw;
        float* op = out + (size_t)d * CPH + lane * 8;
        red_add_v4(op, o0);
        red_add_v4(op + 4, o1);
    }
}

// ---------------- launch (fork-join: CSR + zero_out + gate overlap GEMM) ----------------
extern "C" void kernel_launch(void* const* d_in, const int* in_sizes, int n_in,
                              void* d_out, int out_size) {
    const float* x      = (const float*)d_in[0];
    const int*   ei0    = (const int*)d_in[1];
    const int*   ei1    = (const int*)d_in[2];
    const int*   ei2    = (const int*)d_in[3];
    const float* W_l    = (const float*)d_in[4];
    const float* b_l    = (const float*)d_in[5];
    const float* W_r    = (const float*)d_in[6];
    const float* b_r    = (const float*)d_in[7];
    const float* att    = (const float*)d_in[8];
    const float* bias   = (const float*)d_in[9];
    const float* W_gate = (const float*)d_in[10];
    const float* b_gate = (const float*)d_in[11];
    float* out = (float*)d_out;

    float* pXL; cudaGetSymbolAddress((void**)&pXL, g_XL);
    float* pXR; cudaGetSymbolAddress((void**)&pXR, g_XR);

    static cudaStream_t s2 = nullptr;
    static cudaEvent_t evF = nullptr, evJ = nullptr;
    if (s2 == nullptr) {
        cudaStreamCreateWithFlags(&s2, cudaStreamNonBlocking);
        cudaEventCreateWithFlags(&evF, cudaEventDisableTiming);
        cudaEventCreateWithFlags(&evJ, cudaEventDisableTiming);
    }

    // fork: side stream does CSR build + out-zero + gate while main does GEMM
    cudaEventRecord(evF, 0);
    cudaStreamWaitEvent(s2, evF, 0);

    dim3 eg((EDGES + 255) / 256, HOPS);
    zero_cnt<<<(HOPS * NNODES / 4 + 255) / 256, 256, 0, s2>>>();
    zero_out<<<(NNODES * CPH / 4 + 255) / 256, 256, 0, s2>>>(out);
    gate_kernel<<<(NNODES + 7) / 8, 256, 0, s2>>>(x, W_gate, b_gate);
    count_kernel<<<eg, 256, 0, s2>>>(ei0, ei1, ei2);
    scan1_kernel<<<dim3(NSCANB, HOPS), 256, 0, s2>>>();
    scan2_kernel<<<HOPS, 32, 0, s2>>>();
    scan3_kernel<<<dim3((NNODES + 255) / 256, HOPS), 256, 0, s2>>>();
    scatter_kernel<<<eg, 256, 0, s2>>>(ei0, ei1, ei2);
    cudaEventRecord(evJ, s2);

    // main stream: projections
    sgemm2_dual<<<dim3(2, (NNODES + 127) / 128, 2), 256>>>(x, W_l, b_l, W_r, b_r, pXL, pXR);

    // join, then fused attention + aggregation + gating
    cudaStreamWaitEvent(0, evJ, 0);
    aggregate_kernel<<<dim3((NNODES + 7) / 8, HOPS), 256>>>(att, bias, out);
}

// round 14
// speedup vs baseline: 1.0337x; 1.0337x over previous
#include <cuda_runtime.h>
#include <cuda_bf16.h>
#include <cstdint>

// ---------------- problem constants ----------------
#define NNODES 50000
#define INCH   256
#define HEADS  4
#define CPH    64
#define HC     256
#define HOPS   3
#define EDGES  400000
#define NEG_SLOPE 0.2f
#define NSCANB 49               // ceil(50000/1024)

// ---------------- scratch (static device memory) ----------------
__device__ float g_XL[NNODES * HC];
__device__ float g_XR[NNODES * HC];
__device__ float g_GW[NNODES * HOPS];
__device__ int   g_CNT[HOPS * NNODES];
__device__ int   g_ROW[HOPS * NNODES];
__device__ int   g_POS[HOPS * NNODES];
__device__ int   g_BSUM[HOPS][64];
__device__ int   g_CSR[HOPS * EDGES];
__device__ int2  g_META[HOPS * NNODES];   // (row_start, count)

// ---------------- helpers ----------------
__device__ __forceinline__ float lrelu(float v) { return v > 0.f ? v : NEG_SLOPE * v; }

__device__ __forceinline__ void red_add_v4(float* p, float4 v) {
    asm volatile("red.global.add.v4.f32 [%0], {%1,%2,%3,%4};"
                 :: "l"(p), "f"(v.x), "f"(v.y), "f"(v.z), "f"(v.w) : "memory");
}
__device__ __forceinline__ unsigned long long pack_dup(float v) {
    unsigned long long d;
    asm("mov.b64 %0, {%1, %1};" : "=l"(d) : "r"(__float_as_uint(v)));
    return d;
}
__device__ __forceinline__ void ffma2(unsigned long long& acc,
                                      unsigned long long a, unsigned long long b) {
    asm("fma.rn.f32x2 %0, %1, %2, %0;" : "+l"(acc) : "l"(a), "l"(b));
}
__device__ __forceinline__ void unpack2(unsigned long long p, float& lo, float& hi) {
    unsigned l, h;
    asm("mov.b64 {%0, %1}, %2;" : "=r"(l), "=r"(h) : "l"(p));
    lo = __uint_as_float(l); hi = __uint_as_float(h);
}

// per-edge logit: lrelu(xl+xr).att, reduced over the 8 lanes of each head
__device__ __forceinline__ float edge_logit(float4 a0, float4 a1,
                                            float4 r0, float4 r1,
                                            float4 t0, float4 t1) {
    float p = lrelu(a0.x + r0.x) * t0.x + lrelu(a0.y + r0.y) * t0.y
            + lrelu(a0.z + r0.z) * t0.z + lrelu(a0.w + r0.w) * t0.w
            + lrelu(a1.x + r1.x) * t1.x + lrelu(a1.y + r1.y) * t1.y
            + lrelu(a1.z + r1.z) * t1.z + lrelu(a1.w + r1.w) * t1.w;
    p += __shfl_xor_sync(0xffffffffu, p, 1);
    p += __shfl_xor_sync(0xffffffffu, p, 2);
    p += __shfl_xor_sync(0xffffffffu, p, 4);
    return p;
}

// ---------------- zero: counters (side stream) ----------------
__global__ __launch_bounds__(256)
void zero_cnt() {
    int i = blockIdx.x * blockDim.x + threadIdx.x;
    if (i < HOPS * NNODES / 4)
        ((int4*)g_CNT)[i] = make_int4(0, 0, 0, 0);
}
// ---------------- zero: output (side stream) ----------------
__global__ __launch_bounds__(256)
void zero_out(float* __restrict__ out) {
    int i = blockIdx.x * blockDim.x + threadIdx.x;
    if (i < NNODES * CPH / 4)
        ((float4*)out)[i] = make_float4(0.f, 0.f, 0.f, 0.f);
}

// ---------------- SGEMM (packed f32x2), both weights via blockIdx.z ----------------
__global__ __launch_bounds__(256)
void sgemm2_dual(const float* __restrict__ A,
                 const float* __restrict__ WL, const float* __restrict__ bL,
                 const float* __restrict__ WR, const float* __restrict__ bR,
                 float* __restrict__ XL, float* __restrict__ XR) {
    __shared__ unsigned long long Asd[2][8][128];
    __shared__ float Bs[2][8][128];

    const float* B    = blockIdx.z ? WR : WL;
    const float* bias = blockIdx.z ? bR : bL;
    float*       Cm   = blockIdx.z ? XR : XL;

    const int tid = threadIdx.x;
    const int tx = tid & 15, ty = tid >> 4;
    const int row0 = blockIdx.y * 128;
    const int col0 = blockIdx.x * 128;
    const int aRow = tid >> 1, aCol = (tid & 1) * 4;
    const int bRow = tid >> 5, bCol = (tid & 31) * 4;

    unsigned long long acc[8][4];
    #pragma unroll
    for (int i = 0; i < 8; i++)
        #pragma unroll
        for (int j = 0; j < 4; j++) acc[i][j] = 0ull;

    {
        float4 av = make_float4(0.f, 0.f, 0.f, 0.f);
        if (row0 + aRow < NNODES)
            av = *(const float4*)(A + (size_t)(row0 + aRow) * 256 + aCol);
        Asd[0][aCol + 0][aRow] = pack_dup(av.x);
        Asd[0][aCol + 1][aRow] = pack_dup(av.y);
        Asd[0][aCol + 2][aRow] = pack_dup(av.z);
        Asd[0][aCol + 3][aRow] = pack_dup(av.w);
        *(float4*)&Bs[0][bRow][bCol] =
            *(const float4*)(B + (size_t)bRow * 256 + col0 + bCol);
    }
    __syncthreads();

    #pragma unroll 1
    for (int kt = 0; kt < 32; kt++) {
        const int cur = kt & 1, nxt = cur ^ 1;
        float4 av, bv;
        const bool pf = (kt < 31);
        if (pf) {
            av = make_float4(0.f, 0.f, 0.f, 0.f);
            if (row0 + aRow < NNODES)
                av = *(const float4*)(A + (size_t)(row0 + aRow) * 256 + (kt + 1) * 8 + aCol);
            bv = *(const float4*)(B + (size_t)((kt + 1) * 8 + bRow) * 256 + col0 + bCol);
        }

        #pragma unroll
        for (int k = 0; k < 8; k++) {
            unsigned long long ad[8], bp[4];
            *(ulonglong2*)&ad[0] = *(ulonglong2*)&Asd[cur][k][ty * 8 + 0];
            *(ulonglong2*)&ad[2] = *(ulonglong2*)&Asd[cur][k][ty * 8 + 2];
            *(ulonglong2*)&ad[4] = *(ulonglong2*)&Asd[cur][k][ty * 8 + 4];
            *(ulonglong2*)&ad[6] = *(ulonglong2*)&Asd[cur][k][ty * 8 + 6];
            *(ulonglong2*)&bp[0] = *(ulonglong2*)&Bs[cur][k][tx * 8 + 0];
            *(ulonglong2*)&bp[2] = *(ulonglong2*)&Bs[cur][k][tx * 8 + 4];
            #pragma unroll
            for (int i = 0; i < 8; i++)
                #pragma unroll
                for (int j = 0; j < 4; j++)
                    ffma2(acc[i][j], ad[i], bp[j]);
        }

        if (pf) {
            Asd[nxt][aCol + 0][aRow] = pack_dup(av.x);
            Asd[nxt][aCol + 1][aRow] = pack_dup(av.y);
            Asd[nxt][aCol + 2][aRow] = pack_dup(av.z);
            Asd[nxt][aCol + 3][aRow] = pack_dup(av.w);
            *(float4*)&Bs[nxt][bRow][bCol] = bv;
        }
        __syncthreads();
    }

    #pragma unroll
    for (int i = 0; i < 8; i++) {
        int r = row0 + ty * 8 + i;
        if (r < NNODES) {
            #pragma unroll
            for (int j = 0; j < 4; j += 2) {
                int cc = col0 + tx * 8 + j * 2;
                float4 o;
                unpack2(acc[i][j + 0], o.x, o.y);
                unpack2(acc[i][j + 1], o.z, o.w);
                o.x += bias[cc + 0]; o.y += bias[cc + 1];
                o.z += bias[cc + 2]; o.w += bias[cc + 3];
                *(float4*)(Cm + (size_t)r * 256 + cc) = o;
            }
        }
    }
}

// ---------------- gate ----------------
__global__ __launch_bounds__(256)
void gate_kernel(const float* __restrict__ x, const float* __restrict__ Wg,
                 const float* __restrict__ bg) {
    int n = blockIdx.x * 8 + (threadIdx.x >> 5);
    if (n >= NNODES) return;
    int lane = threadIdx.x & 31;
    const float* xr = x + (size_t)n * INCH;
    float p0 = 0.f, p1 = 0.f, p2 = 0.f;
    #pragma unroll
    for (int i = 0; i < INCH; i += 32) {
        float xv = xr[i + lane];
        const float* w = Wg + (i + lane) * 3;
        p0 = fmaf(xv, w[0], p0);
        p1 = fmaf(xv, w[1], p1);
        p2 = fmaf(xv, w[2], p2);
    }
    #pragma unroll
    for (int o = 16; o >= 1; o >>= 1) {
        p0 += __shfl_xor_sync(0xffffffffu, p0, o);
        p1 += __shfl_xor_sync(0xffffffffu, p1, o);
        p2 += __shfl_xor_sync(0xffffffffu, p2, o);
    }
    if (lane == 0) {
        p0 += bg[0]; p1 += bg[1]; p2 += bg[2];
        float m = fmaxf(p0, fmaxf(p1, p2));
        float e0 = __expf(p0 - m), e1 = __expf(p1 - m), e2 = __expf(p2 - m);
        float inv = 1.f / (e0 + e1 + e2);
        g_GW[n * 3 + 0] = e0 * inv;
        g_GW[n * 3 + 1] = e1 * inv;
        g_GW[n * 3 + 2] = e2 * inv;
    }
}

// ---------------- CSR build: count / scan / scatter ----------------
__global__ __launch_bounds__(256)
void count_kernel(const int* __restrict__ ei0, const int* __restrict__ ei1,
                  const int* __restrict__ ei2) {
    int hop = blockIdx.y;
    const int* ei = hop == 0 ? ei0 : (hop == 1 ? ei1 : ei2);
    int e = blockIdx.x * 256 + threadIdx.x;
    if (e < EDGES)
        atomicAdd(&g_CNT[hop * NNODES + ei[EDGES + e]], 1);
}

__global__ __launch_bounds__(256)
void scan1_kernel() {
    __shared__ int ws[8];
    int hop = blockIdx.y;
    int base = blockIdx.x * 1024 + threadIdx.x * 4;
    int lane = threadIdx.x & 31, warp = threadIdx.x >> 5;
    int v[4];
    #pragma unroll
    for (int j = 0; j < 4; j++)
        v[j] = (base + j < NNODES) ? g_CNT[hop * NNODES + base + j] : 0;
    int ts = v[0] + v[1] + v[2] + v[3];
    int is = ts;
    #pragma unroll
    for (int o = 1; o < 32; o <<= 1) {
        int t = __shfl_up_sync(0xffffffffu, is, o);
        if (lane >= o) is += t;
    }
    if (lane == 31) ws[warp] = is;
    __syncthreads();
    if (threadIdx.x == 0) {
        int s = 0;
        #pragma unroll
        for (int i = 0; i < 8; i++) { int t = ws[i]; ws[i] = s; s += t; }
        g_BSUM[hop][blockIdx.x] = s;
    }
    __syncthreads();
    int excl = ws[warp] + is - ts;
    #pragma unroll
    for (int j = 0; j < 4; j++) {
        if (base + j < NNODES) g_ROW[hop * NNODES + base + j] = excl;
        excl += v[j];
    }
}

__global__ __launch_bounds__(32)
void scan2_kernel() {
    int hop = blockIdx.x, l = threadIdx.x;
    int a = (l < NSCANB) ? g_BSUM[hop][l] : 0;
    int b = (32 + l < NSCANB) ? g_BSUM[hop][32 + l] : 0;
    int sa = a;
    #pragma unroll
    for (int o = 1; o < 32; o <<= 1) {
        int t = __shfl_up_sync(0xffffffffu, sa, o);
        if (l >= o) sa += t;
    }
    int tot = __shfl_sync(0xffffffffu, sa, 31);
    int sb = b;
    #pragma unroll
    for (int o = 1; o < 32; o <<= 1) {
        int t = __shfl_up_sync(0xffffffffu, sb, o);
        if (l >= o) sb += t;
    }
    sb += tot;
    if (l < NSCANB) g_BSUM[hop][l] = sa - a;
    if (32 + l < NSCANB) g_BSUM[hop][32 + l] = sb - b;
}

__global__ __launch_bounds__(256)
void scan3_kernel() {
    int hop = blockIdx.y;
    int i = blockIdx.x * 256 + threadIdx.x;
    if (i < NNODES) {
        int r = g_ROW[hop * NNODES + i] + g_BSUM[hop][i >> 10];
        g_POS[hop * NNODES + i] = r;
        g_META[hop * NNODES + i] = make_int2(r, g_CNT[hop * NNODES + i]);
    }
}

__global__ __launch_bounds__(256)
void scatter_kernel(const int* __restrict__ ei0, const int* __restrict__ ei1,
                    const int* __restrict__ ei2) {
    int hop = blockIdx.y;
    const int* ei = hop == 0 ? ei0 : (hop == 1 ? ei1 : ei2);
    int e = blockIdx.x * 256 + threadIdx.x;
    if (e < EDGES) {
        int d = ei[EDGES + e];
        int p = atomicAdd(&g_POS[hop * NNODES + d], 1);
        g_CSR[hop * EDGES + p] = ei[e];
    }
}

// ---------------- aggregate: warp per (hop, dst), shfl-broadcast indices ----------------
__global__ __launch_bounds__(256)
void aggregate_kernel(const float* __restrict__ att, const float* __restrict__ bias,
                      float* __restrict__ out) {
    int hop = blockIdx.y;
    int d = blockIdx.x * 8 + (threadIdx.x >> 5);
    if (d >= NNODES) return;
    int lane = threadIdx.x & 31;

    int2 meta = __ldg(&g_META[hop * NNODES + d]);   // (row_start, count)
    const int* srcs = g_CSR + (size_t)hop * EDGES + meta.x;
    int cnt = meta.y;

    // coalesced fetch of up to 32 neighbor indices into a register (one per lane)
    int idxreg = (lane < cnt) ? __ldg(srcs + lane) : 0;

    const float4* xr4 = (const float4*)(g_XR + (size_t)d * HC) + lane * 2;
    float4 r0 = xr4[0], r1 = xr4[1];
    float4 t0 = __ldg((const float4*)(att + hop * HC) + lane * 2);
    float4 t1 = __ldg((const float4*)(att + hop * HC) + lane * 2 + 1);

    float acc[8];
    #pragma unroll
    for (int j = 0; j < 8; j++) acc[j] = 0.f;
    float sumh = 0.f;

    if (hop == 0) {   // self loop: src == d
        const float4* xs = (const float4*)(g_XL + (size_t)d * HC) + lane * 2;
        float4 a0 = xs[0], a1 = xs[1];
        float p = edge_logit(a0, a1, r0, r1, t0, t1);
        float ex = __expf(p);
        sumh = ex;
        acc[0] = ex * a0.x; acc[1] = ex * a0.y; acc[2] = ex * a0.z; acc[3] = ex * a0.w;
        acc[4] = ex * a1.x; acc[5] = ex * a1.y; acc[6] = ex * a1.z; acc[7] = ex * a1.w;
    }

    int reg_cnt = cnt < 32 ? cnt : 32;
    int e = 0;
    #pragma unroll 1
    for (; e + 2 <= reg_cnt; e += 2) {
        int s0 = __shfl_sync(0xffffffffu, idxreg, e);
        int s1 = __shfl_sync(0xffffffffu, idxreg, e + 1);
        const float4* x0 = (const float4*)(g_XL + (size_t)s0 * HC) + lane * 2;
        const float4* x1 = (const float4*)(g_XL + (size_t)s1 * HC) + lane * 2;
        float4 a00 = x0[0], a01 = x0[1];
        float4 a10 = x1[0], a11 = x1[1];

        float p0 = edge_logit(a00, a01, r0, r1, t0, t1);
        float p1 = edge_logit(a10, a11, r0, r1, t0, t1);
        float e0 = __expf(p0), e1 = __expf(p1);
        sumh += e0 + e1;

        acc[0] = fmaf(e0, a00.x, acc[0]); acc[1] = fmaf(e0, a00.y, acc[1]);
        acc[2] = fmaf(e0, a00.z, acc[2]); acc[3] = fmaf(e0, a00.w, acc[3]);
        acc[4] = fmaf(e0, a01.x, acc[4]); acc[5] = fmaf(e0, a01.y, acc[5]);
        acc[6] = fmaf(e0, a01.z, acc[6]); acc[7] = fmaf(e0, a01.w, acc[7]);

        acc[0] = fmaf(e1, a10.x, acc[0]); acc[1] = fmaf(e1, a10.y, acc[1]);
        acc[2] = fmaf(e1, a10.z, acc[2]); acc[3] = fmaf(e1, a10.w, acc[3]);
        acc[4] = fmaf(e1, a11.x, acc[4]); acc[5] = fmaf(e1, a11.y, acc[5]);
        acc[6] = fmaf(e1, a11.z, acc[6]); acc[7] = fmaf(e1, a11.w, acc[7]);
    }
    if (e < reg_cnt) {
        int s = __shfl_sync(0xffffffffu, idxreg, e);
        const float4* xs = (const float4*)(g_XL + (size_t)s * HC) + lane * 2;
        float4 a0 = xs[0], a1 = xs[1];
        float p = edge_logit(a0, a1, r0, r1, t0, t1);
        float ex = __expf(p);
        sumh += ex;
        acc[0] = fmaf(ex, a0.x, acc[0]); acc[1] = fmaf(ex, a0.y, acc[1]);
        acc[2] = fmaf(ex, a0.z, acc[2]); acc[3] = fmaf(ex, a0.w, acc[3]);
        acc[4] = fmaf(ex, a1.x, acc[4]); acc[5] = fmaf(ex, a1.y, acc[5]);
        acc[6] = fmaf(ex, a1.z, acc[6]); acc[7] = fmaf(ex, a1.w, acc[7]);
    }
    // rare overflow tail (degree > 32)
    #pragma unroll 1
    for (e = 32; e < cnt; e++) {
        int s = __ldg(srcs + e);
        const float4* xs = (const float4*)(g_XL + (size_t)s * HC) + lane * 2;
        float4 a0 = xs[0], a1 = xs[1];
        float p = edge_logit(a0, a1, r0, r1, t0, t1);
        float ex = __expf(p);
        sumh += ex;
        acc[0] = fmaf(ex, a0.x, acc[0]); acc[1] = fmaf(ex, a0.y, acc[1]);
        acc[2] = fmaf(ex, a0.z, acc[2]); acc[3] = fmaf(ex, a0.w, acc[3]);
        acc[4] = fmaf(ex, a1.x, acc[4]); acc[5] = fmaf(ex, a1.y, acc[5]);
        acc[6] = fmaf(ex, a1.z, acc[6]); acc[7] = fmaf(ex, a1.w, acc[7]);
    }

    float inv = 1.f / (sumh + 1e-16f);
    float r[8];
    #pragma unroll
    for (int j = 0; j < 8; j++) r[j] = acc[j] * inv;
    // mean over heads: combine lanes l, l^8, l^16, l^24
    #pragma unroll
    for (int j = 0; j < 8; j++) {
        r[j] += __shfl_xor_sync(0xffffffffu, r[j], 8);
        r[j] += __shfl_xor_sync(0xffffffffu, r[j], 16);
    }
    if (lane < 8) {
        float gw = g_GW[d * HOPS + hop];
        const float* bb = bias + hop * CPH + lane * 8;
        float4 o0, o1;
        o0.x = (r[0] * 0.25f + __ldg(bb + 0)) * gw;
        o0.y = (r[1] * 0.25f + __ldg(bb + 1)) * gw;
        o0.z = (r[2] * 0.25f + __ldg(bb + 2)) * gw;
        o0.w = (r[3] * 0.25f + __ldg(bb + 3)) * gw;
        o1.x = (r[4] * 0.25f + __ldg(bb + 4)) * gw;
        o1.y = (r[5] * 0.25f + __ldg(bb + 5)) * gw;
        o1.z = (r[6] * 0.25f + __ldg(bb + 6)) * gw;
        o1.w = (r[7] * 0.25f + __ldg(bb + 7)) * gw;
        float* op = out + (size_t)d * CPH + lane * 8;
        red_add_v4(op, o0);
        red_add_v4(op + 4, o1);
    }
}

// ---------------- launch (fork-join: CSR + zero_out + gate overlap GEMM) ----------------
extern "C" void kernel_launch(void* const* d_in, const int* in_sizes, int n_in,
                              void* d_out, int out_size) {
    const float* x      = (const float*)d_in[0];
    const int*   ei0    = (const int*)d_in[1];
    const int*   ei1    = (const int*)d_in[2];
    const int*   ei2    = (const int*)d_in[3];
    const float* W_l    = (const float*)d_in[4];
    const float* b_l    = (const float*)d_in[5];
    const float* W_r    = (const float*)d_in[6];
    const float* b_r    = (const float*)d_in[7];
    const float* att    = (const float*)d_in[8];
    const float* bias   = (const float*)d_in[9];
    const float* W_gate = (const float*)d_in[10];
    const float* b_gate = (const float*)d_in[11];
    float* out = (float*)d_out;

    float* pXL; cudaGetSymbolAddress((void**)&pXL, g_XL);
    float* pXR; cudaGetSymbolAddress((void**)&pXR, g_XR);

    static cudaStream_t s2 = nullptr;
    static cudaEvent_t evF = nullptr, evJ = nullptr;
    if (s2 == nullptr) {
        cudaStreamCreateWithFlags(&s2, cudaStreamNonBlocking);
        cudaEventCreateWithFlags(&evF, cudaEventDisableTiming);
        cudaEventCreateWithFlags(&evJ, cudaEventDisableTiming);
    }

    // fork: side stream does CSR build + out-zero + gate while main does GEMM
    cudaEventRecord(evF, 0);
    cudaStreamWaitEvent(s2, evF, 0);

    dim3 eg((EDGES + 255) / 256, HOPS);
    zero_cnt<<<(HOPS * NNODES / 4 + 255) / 256, 256, 0, s2>>>();
    zero_out<<<(NNODES * CPH / 4 + 255) / 256, 256, 0, s2>>>(out);
    gate_kernel<<<(NNODES + 7) / 8, 256, 0, s2>>>(x, W_gate, b_gate);
    count_kernel<<<eg, 256, 0, s2>>>(ei0, ei1, ei2);
    scan1_kernel<<<dim3(NSCANB, HOPS), 256, 0, s2>>>();
    scan2_kernel<<<HOPS, 32, 0, s2>>>();
    scan3_kernel<<<dim3((NNODES + 255) / 256, HOPS), 256, 0, s2>>>();
    scatter_kernel<<<eg, 256, 0, s2>>>(ei0, ei1, ei2);
    cudaEventRecord(evJ, s2);

    // main stream: projections
    sgemm2_dual<<<dim3(2, (NNODES + 127) / 128, 2), 256>>>(x, W_l, b_l, W_r, b_r, pXL, pXR);

    // join, then fused attention + aggregation + gating
    cudaStreamWaitEvent(0, evJ, 0);
    aggregate_kernel<<<dim3((NNODES + 7) / 8, HOPS), 256>>>(att, bias, out);
}